// round 1
// baseline (speedup 1.0000x reference)
#include <cuda_runtime.h>

#define HIDDEN 300
#define HP 320            // padded hidden stride
#define NEDGE 102400
#define NNODE 51200
#define NMOL 2048
#define FEK 160           // padded EDGE_FDIM (147)
#define AOK 448           // padded NODE_FDIM+HIDDEN (433)
#define NODE_FDIM 133
#define EDGE_FDIM 147
#define MAXNB 6

// ---------------- scratch (device globals; no allocations allowed) ----------------
static __device__ float g_inp [NEDGE * HP];
static __device__ float g_msgA[NEDGE * HP];
static __device__ float g_msgB[NEDGE * HP];
static __device__ float g_nmsg[NNODE * HP];
static __device__ float g_fep [NEDGE * FEK];
static __device__ float g_ain [NNODE * AOK];
static __device__ float g_hid [NNODE * HP];
static __device__ float g_Wip [FEK * HP];
static __device__ float g_Whp [HP  * HP];
static __device__ float g_Wop [AOK * HP];
static __device__ float g_bop [HP];

// ---------------- f32x2 packed-FMA helpers (sm_100a) ----------------
__device__ __forceinline__ unsigned long long pk2(float x, float y) {
    unsigned long long r;
    asm("mov.b64 %0, {%1, %2};" : "=l"(r) : "f"(x), "f"(y));
    return r;
}
__device__ __forceinline__ void fma2(unsigned long long& d, unsigned long long a, unsigned long long b) {
    asm("fma.rn.f32x2 %0, %1, %2, %0;" : "+l"(d) : "l"(a), "l"(b));
}
__device__ __forceinline__ float2 up2(unsigned long long v) {
    float2 r;
    asm("mov.b64 {%0, %1}, %2;" : "=f"(r.x), "=f"(r.y) : "l"(v));
    return r;
}

// ---------------- padding kernels ----------------
__global__ void k_pad_w(const float* __restrict__ W, float* __restrict__ Wp,
                        int Kreal, int total) {
    int idx = blockIdx.x * blockDim.x + threadIdx.x;
    if (idx >= total) return;
    int k = idx / HP, n = idx % HP;
    Wp[idx] = (k < Kreal && n < HIDDEN) ? W[k * HIDDEN + n] : 0.f;
}

__global__ void k_pad_fe(const float* __restrict__ fe, float* __restrict__ fep) {
    int idx = blockIdx.x * blockDim.x + threadIdx.x;  // NEDGE*FEK exact
    int r = idx / FEK, c = idx % FEK;
    fep[idx] = (c < EDGE_FDIM) ? fe[r * EDGE_FDIM + c] : 0.f;
}

__global__ void k_pad_bo(const float* __restrict__ b, float* __restrict__ bp) {
    int i = threadIdx.x;
    if (i < HP) bp[i] = (i < HIDDEN) ? b[i] : 0.f;
}

// ---------------- neighbor sum: nmsg[v] = sum_j msg[n2e[v][j]] ----------------
__global__ void k_nodesum(const float* __restrict__ msg, const int* __restrict__ n2e,
                          float* __restrict__ nmsg) {
    int idx = blockIdx.x * blockDim.x + threadIdx.x;  // NNODE*80 exact
    int v = idx / (HP / 4);
    int q = (idx % (HP / 4)) * 4;
    const int* nb = n2e + v * MAXNB;
    float4 s = make_float4(0.f, 0.f, 0.f, 0.f);
#pragma unroll
    for (int j = 0; j < MAXNB; j++) {
        int e = __ldg(nb + j);
        float4 a = *reinterpret_cast<const float4*>(msg + (long)e * HP + q);
        s.x += a.x; s.y += a.y; s.z += a.z; s.w += a.w;
    }
    *reinterpret_cast<float4*>(nmsg + (long)v * HP + q) = s;
}

// ---------------- build a_input = [f_nodes | nmsg | 0pad] ----------------
__global__ void k_build_ain(const float* __restrict__ fn, const float* __restrict__ nmsg,
                            float* __restrict__ ain) {
    int idx = blockIdx.x * blockDim.x + threadIdx.x;  // NNODE*AOK exact
    int v = idx / AOK, c = idx % AOK;
    float val;
    if (c < NODE_FDIM)      val = fn[(long)v * NODE_FDIM + c];
    else if (c < NODE_FDIM + HIDDEN) val = nmsg[(long)v * HP + (c - NODE_FDIM)];
    else                    val = 0.f;
    ain[idx] = val;
}

// ---------------- GEMM: C[M,320] = A[M,K] @ B[K,320] (+epilogue) ----------------
// MODE 1: A row = nmsg[e2n[r]] - msg[e2rev[r]]; C0 = relu(inp + A@B)
// MODE 2: C0 = A@B (inp), C1 = relu(A@B) (msg)
// MODE 3: C0 = relu(A@B + bias)
template <int MODE>
__global__ void __launch_bounds__(256)
k_gemm(const float* __restrict__ A, int lda, int K,
       const float* __restrict__ B,
       const float* __restrict__ inp,
       const float* __restrict__ bias,
       float* __restrict__ C0, float* __restrict__ C1,
       const int* __restrict__ e2n, const int* __restrict__ e2rev,
       const float* __restrict__ nmsg, const float* __restrict__ msg) {
    constexpr int BM = 128, BN = 160, BK = 16;
    __shared__ __align__(16) float As[2][BK][BM];
    __shared__ __align__(16) float Bs[2][BK][BN];

    int tid  = threadIdx.x;
    int rowA = tid >> 1;             // 0..127
    int c0   = (tid & 1) * 8;        // 0 or 8 within BK
    int grow = blockIdx.y * BM + rowA;
    int nBase = blockIdx.x * BN;

    const float* arow0;
    const float* arow1 = nullptr;
    if constexpr (MODE == 1) {
        arow0 = nmsg + (long)__ldg(e2n  + grow) * HP;
        arow1 = msg  + (long)__ldg(e2rev + grow) * HP;
    } else {
        arow0 = A + (long)grow * lda;
    }

    int ty = tid >> 4, tx = tid & 15;
    int m0 = ty * 8, n0 = tx * 10;

    unsigned long long acc[8][5];
#pragma unroll
    for (int i = 0; i < 8; i++)
#pragma unroll
        for (int j = 0; j < 5; j++) acc[i][j] = 0ULL;

    const int ntiles = K / BK;

    float4 ra0, ra1;
    float4 rb[3];

    auto loadG = [&](int kt) {
        int k0 = kt * BK;
        if constexpr (MODE == 1) {
            float4 x0 = *(const float4*)(arow0 + k0 + c0);
            float4 y0 = *(const float4*)(arow1 + k0 + c0);
            ra0 = make_float4(x0.x - y0.x, x0.y - y0.y, x0.z - y0.z, x0.w - y0.w);
            float4 x1 = *(const float4*)(arow0 + k0 + c0 + 4);
            float4 y1 = *(const float4*)(arow1 + k0 + c0 + 4);
            ra1 = make_float4(x1.x - y1.x, x1.y - y1.y, x1.z - y1.z, x1.w - y1.w);
        } else {
            ra0 = *(const float4*)(arow0 + k0 + c0);
            ra1 = *(const float4*)(arow0 + k0 + c0 + 4);
        }
#pragma unroll
        for (int i = 0; i < 3; i++) {
            int f = tid + 256 * i;
            if (f < (BK * BN) / 4) {
                int kk = f / (BN / 4), cc = (f % (BN / 4)) * 4;
                rb[i] = *(const float4*)(B + (long)(k0 + kk) * HP + nBase + cc);
            }
        }
    };
    auto storeS = [&](int buf) {
        As[buf][c0 + 0][rowA] = ra0.x; As[buf][c0 + 1][rowA] = ra0.y;
        As[buf][c0 + 2][rowA] = ra0.z; As[buf][c0 + 3][rowA] = ra0.w;
        As[buf][c0 + 4][rowA] = ra1.x; As[buf][c0 + 5][rowA] = ra1.y;
        As[buf][c0 + 6][rowA] = ra1.z; As[buf][c0 + 7][rowA] = ra1.w;
#pragma unroll
        for (int i = 0; i < 3; i++) {
            int f = tid + 256 * i;
            if (f < (BK * BN) / 4) {
                int kk = f / (BN / 4), cc = (f % (BN / 4)) * 4;
                *(float4*)&Bs[buf][kk][cc] = rb[i];
            }
        }
    };

    loadG(0);
    storeS(0);
    __syncthreads();

    for (int kt = 0; kt < ntiles; kt++) {
        if (kt + 1 < ntiles) loadG(kt + 1);
        int buf = kt & 1;
#pragma unroll
        for (int k = 0; k < BK; k++) {
            float4 t0 = *(const float4*)&As[buf][k][m0];
            float4 t1 = *(const float4*)&As[buf][k][m0 + 4];
            unsigned long long a2[8];
            a2[0] = pk2(t0.x, t0.x); a2[1] = pk2(t0.y, t0.y);
            a2[2] = pk2(t0.z, t0.z); a2[3] = pk2(t0.w, t0.w);
            a2[4] = pk2(t1.x, t1.x); a2[5] = pk2(t1.y, t1.y);
            a2[6] = pk2(t1.z, t1.z); a2[7] = pk2(t1.w, t1.w);
            unsigned long long b2[5];
#pragma unroll
            for (int j = 0; j < 5; j++)
                b2[j] = *(const unsigned long long*)&Bs[buf][k][n0 + 2 * j];
#pragma unroll
            for (int i = 0; i < 8; i++)
#pragma unroll
                for (int j = 0; j < 5; j++) fma2(acc[i][j], a2[i], b2[j]);
        }
        if (kt + 1 < ntiles) {
            storeS((kt + 1) & 1);
            __syncthreads();
        }
    }

    // epilogue
    int gmb = blockIdx.y * BM + m0;
#pragma unroll
    for (int i = 0; i < 8; i++) {
        long rbase = (long)(gmb + i) * HP + nBase + n0;
#pragma unroll
        for (int j = 0; j < 5; j++) {
            float2 v = up2(acc[i][j]);
            if constexpr (MODE == 2) {
                *(float2*)(C0 + rbase + 2 * j) = v;
                float2 r = make_float2(fmaxf(v.x, 0.f), fmaxf(v.y, 0.f));
                *(float2*)(C1 + rbase + 2 * j) = r;
            } else if constexpr (MODE == 1) {
                float2 iv = *(const float2*)(inp + rbase + 2 * j);
                float2 r = make_float2(fmaxf(v.x + iv.x, 0.f), fmaxf(v.y + iv.y, 0.f));
                *(float2*)(C0 + rbase + 2 * j) = r;
            } else {
                float2 bv = *(const float2*)(bias + nBase + n0 + 2 * j);
                float2 r = make_float2(fmaxf(v.x + bv.x, 0.f), fmaxf(v.y + bv.y, 0.f));
                *(float2*)(C0 + rbase + 2 * j) = r;
            }
        }
    }
}

// ---------------- per-molecule mean (deterministic; mol_ids sorted) ----------------
__global__ void k_segmean(const float* __restrict__ hid, const int* __restrict__ mol,
                          float* __restrict__ out) {
    int m = blockIdx.x;
    int c = threadIdx.x;
    // lower_bound(m)
    int lo = 0, hi = NNODE;
    while (lo < hi) { int mid = (lo + hi) >> 1; if (__ldg(mol + mid) < m) lo = mid + 1; else hi = mid; }
    int start = lo;
    // lower_bound(m+1)
    lo = start; hi = NNODE;
    while (lo < hi) { int mid = (lo + hi) >> 1; if (__ldg(mol + mid) < m + 1) lo = mid + 1; else hi = mid; }
    int end = lo;
    if (c >= HIDDEN) return;
    float s = 0.f;
    for (int v = start; v < end; v++) s += hid[(long)v * HP + c];
    out[(long)m * HIDDEN + c] = (end > start) ? s / (float)(end - start) : 0.f;
}

// ---------------- launch ----------------
extern "C" void kernel_launch(void* const* d_in, const int* in_sizes, int n_in,
                              void* d_out, int out_size) {
    const float* f_nodes = (const float*)d_in[0];
    const float* f_edges = (const float*)d_in[1];
    const float* W_i     = (const float*)d_in[2];
    const float* W_h     = (const float*)d_in[3];
    const float* W_o     = (const float*)d_in[4];
    const float* b_o     = (const float*)d_in[5];
    const int*   n2e     = (const int*)d_in[6];
    const int*   e2n     = (const int*)d_in[7];
    const int*   e2rev   = (const int*)d_in[8];
    const int*   mol     = (const int*)d_in[9];
    float* out = (float*)d_out;

    float *inp, *msgA, *msgB, *nmsg, *fep, *ain, *hid, *Wip, *Whp, *Wop, *bop;
    cudaGetSymbolAddress((void**)&inp,  g_inp);
    cudaGetSymbolAddress((void**)&msgA, g_msgA);
    cudaGetSymbolAddress((void**)&msgB, g_msgB);
    cudaGetSymbolAddress((void**)&nmsg, g_nmsg);
    cudaGetSymbolAddress((void**)&fep,  g_fep);
    cudaGetSymbolAddress((void**)&ain,  g_ain);
    cudaGetSymbolAddress((void**)&hid,  g_hid);
    cudaGetSymbolAddress((void**)&Wip,  g_Wip);
    cudaGetSymbolAddress((void**)&Whp,  g_Whp);
    cudaGetSymbolAddress((void**)&Wop,  g_Wop);
    cudaGetSymbolAddress((void**)&bop,  g_bop);

    // pad weights & features (cheap, deterministic every call)
    k_pad_w<<<(FEK * HP) / 256, 256>>>(W_i, Wip, EDGE_FDIM, FEK * HP);
    k_pad_w<<<(HP * HP) / 256, 256>>>(W_h, Whp, HIDDEN, HP * HP);
    k_pad_w<<<(AOK * HP) / 256, 256>>>(W_o, Wop, NODE_FDIM + HIDDEN, AOK * HP);
    k_pad_bo<<<1, HP>>>(b_o, bop);
    k_pad_fe<<<(NEDGE * FEK) / 256, 256>>>(f_edges, fep);

    dim3 gridE(2, NEDGE / 128);
    dim3 gridN(2, NNODE / 128);

    // inp = f_edges @ W_i ; msgA = relu(inp)
    k_gemm<2><<<gridE, 256>>>(fep, FEK, FEK, Wip, nullptr, nullptr, inp, msgA,
                              nullptr, nullptr, nullptr, nullptr);

    float* cur = msgA;
    float* nxt = msgB;
    for (int t = 0; t < 5; t++) {
        k_nodesum<<<(NNODE * (HP / 4)) / 256, 256>>>(cur, n2e, nmsg);
        k_gemm<1><<<gridE, 256>>>(nullptr, 0, HP, Whp, inp, nullptr, nxt, nullptr,
                                  e2n, e2rev, nmsg, cur);
        float* tmp = cur; cur = nxt; nxt = tmp;
    }

    k_nodesum<<<(NNODE * (HP / 4)) / 256, 256>>>(cur, n2e, nmsg);
    k_build_ain<<<(NNODE * AOK) / 256, 256>>>(f_nodes, nmsg, ain);
    k_gemm<3><<<gridN, 256>>>(ain, AOK, AOK, Wop, nullptr, bop, hid, nullptr,
                              nullptr, nullptr, nullptr, nullptr);

    k_segmean<<<NMOL, HP>>>(hid, mol, out);
}

// round 4
// speedup vs baseline: 1.6658x; 1.6658x over previous
#include <cuda_runtime.h>
#include <cuda_bf16.h>
#include <cstdint>

#define HIDDEN 300
#define HP 320
#define NEDGE 102400
#define NNODE 51200
#define NMOL 2048
#define NODE_FDIM 133
#define EDGE_FDIM 147
#define MAXNB 6
#define KP_I 160
#define KP_H 320
#define KP_O 448

// ---------------- scratch (device globals; no allocations allowed) ----------------
static __device__ float g_inp [NEDGE * HP];
static __device__ float g_msgA[NEDGE * HP];
static __device__ float g_msgB[NEDGE * HP];
static __device__ float g_nmsg[NNODE * HP];
static __device__ float g_hid [NNODE * HP];
static __device__ __align__(16) __nv_bfloat16 g_WiH[HP * KP_I];
static __device__ __align__(16) __nv_bfloat16 g_WiL[HP * KP_I];
static __device__ __align__(16) __nv_bfloat16 g_WhH[HP * KP_H];
static __device__ __align__(16) __nv_bfloat16 g_WhL[HP * KP_H];
static __device__ __align__(16) __nv_bfloat16 g_WoH[HP * KP_O];
static __device__ __align__(16) __nv_bfloat16 g_WoL[HP * KP_O];
static __device__ float g_bop[HP];

// ---------------- helpers ----------------
__device__ __forceinline__ uint32_t s2u(const void* p) {
    uint32_t a;
    asm("{ .reg .u64 t; cvta.to.shared.u64 t, %1; cvt.u32.u64 %0, t; }" : "=r"(a) : "l"(p));
    return a;
}
__device__ __forceinline__ uint32_t lds32(uint32_t a) {
    uint32_t v;
    asm volatile("ld.shared.b32 %0, [%1];" : "=r"(v) : "r"(a));
    return v;
}
__device__ __forceinline__ void sts128(uint32_t a, uint32_t x, uint32_t y, uint32_t z, uint32_t w) {
    asm volatile("st.shared.v4.b32 [%0], {%1,%2,%3,%4};" :: "r"(a), "r"(x), "r"(y), "r"(z), "r"(w) : "memory");
}
__device__ __forceinline__ void cpa16(uint32_t s, const void* g) {
    asm volatile("cp.async.cg.shared.global [%0], [%1], 16;" :: "r"(s), "l"(g) : "memory");
}
__device__ __forceinline__ void cpa_commit() { asm volatile("cp.async.commit_group;" ::: "memory"); }
__device__ __forceinline__ void cpa_wait0() { asm volatile("cp.async.wait_group 0;" ::: "memory"); }
__device__ __forceinline__ void mma16816(float* c, uint32_t a0, uint32_t a1, uint32_t a2, uint32_t a3,
                                         uint32_t b0, uint32_t b1) {
    asm volatile(
        "mma.sync.aligned.m16n8k16.row.col.f32.bf16.bf16.f32 "
        "{%0,%1,%2,%3}, {%4,%5,%6,%7}, {%8,%9}, {%0,%1,%2,%3};"
        : "+f"(c[0]), "+f"(c[1]), "+f"(c[2]), "+f"(c[3])
        : "r"(a0), "r"(a1), "r"(a2), "r"(a3), "r"(b0), "r"(b1));
}
__device__ __forceinline__ uint32_t pkbf(__nv_bfloat16 a, __nv_bfloat16 b) {
    __nv_bfloat162 h;
    h.x = a; h.y = b;
    return reinterpret_cast<uint32_t&>(h);
}

// SMEM layout: sA tiles (buf,hl): off = (buf*2+hl)*10240      (128 rows x 40 bf16)
//              sB tiles (buf,hl): 40960 + (buf*2+hl)*12800    (160 rows x 40 bf16)
static constexpr int SMEM_SZ = 40960 + 4 * 12800;  // 92160

// ---------------- bf16 split mma.sync GEMM ----------------
// C[M,320] = A[M,KP] @ B^T ; 3-product hi/lo compensation.
// MODE 1: A row = nmsg[e2n[r]] - msg[e2rev[r]] (KP=320); C0 = relu(inp + AB)
// MODE 2: A = f_edges (stride 147, pad to 160);          C0 = AB, C1 = relu(AB)
// MODE 3: A row = [f_nodes | nmsg | 0] (KP=448);         C0 = relu(AB + bias)
template <int MODE, int KP>
__global__ void __launch_bounds__(256)
k_mma(const float* __restrict__ Asrc,
      const __nv_bfloat16* __restrict__ Bhi, const __nv_bfloat16* __restrict__ Blo,
      const float* __restrict__ inp, const float* __restrict__ bias,
      float* __restrict__ C0, float* __restrict__ C1,
      const int* __restrict__ e2n, const int* __restrict__ e2rev,
      const float* __restrict__ nmsg, const float* __restrict__ msg) {
    extern __shared__ __align__(16) char smem[];
    uint32_t sb = s2u(smem);
    constexpr int NCH = KP / 32;

    int tid = threadIdx.x, wid = tid >> 5, lane = tid & 31;
    int g = lane >> 2, t = lane & 3;
    int wm = wid & 1, wn = wid >> 1;
    int r = tid >> 1, h = tid & 1;
    int grow = blockIdx.y * 128 + r;
    int nb0 = blockIdx.x * 160;

    const float* arow0 = nullptr;
    const float* arow1 = nullptr;
    if constexpr (MODE == 1) {
        arow0 = nmsg + (size_t)__ldg(e2n + grow) * HP;
        arow1 = msg + (size_t)__ldg(e2rev + grow) * HP;
    } else if constexpr (MODE == 2) {
        arow0 = Asrc + (size_t)grow * EDGE_FDIM;
    } else {
        arow0 = Asrc + (size_t)grow * NODE_FDIM;
        arow1 = nmsg + (size_t)grow * HP;
    }

    float acc[4][5][4];
#pragma unroll
    for (int i = 0; i < 4; i++)
#pragma unroll
        for (int j = 0; j < 5; j++)
#pragma unroll
            for (int q = 0; q < 4; q++) acc[i][j][q] = 0.f;

    float v[16];

    auto loadA = [&](int ch) {
        int c0 = ch * 32 + h * 16;
        if constexpr (MODE == 1) {
#pragma unroll
            for (int q = 0; q < 4; q++) {
                float4 x = *(const float4*)(arow0 + c0 + q * 4);
                float4 y = *(const float4*)(arow1 + c0 + q * 4);
                v[q * 4 + 0] = x.x - y.x; v[q * 4 + 1] = x.y - y.y;
                v[q * 4 + 2] = x.z - y.z; v[q * 4 + 3] = x.w - y.w;
            }
        } else if constexpr (MODE == 2) {
#pragma unroll
            for (int j = 0; j < 16; j++) {
                int c = c0 + j;
                v[j] = (c < EDGE_FDIM) ? __ldg(arow0 + c) : 0.f;
            }
        } else {
#pragma unroll
            for (int j = 0; j < 16; j++) {
                int c = c0 + j;
                v[j] = (c < NODE_FDIM) ? __ldg(arow0 + c)
                     : ((c < NODE_FDIM + HIDDEN) ? __ldg(arow1 + (c - NODE_FDIM)) : 0.f);
            }
        }
    };

    auto storeA = [&](int buf) {
        uint32_t hp[8], lp[8];
#pragma unroll
        for (int j = 0; j < 8; j++) {
            float a = v[2 * j], b = v[2 * j + 1];
            __nv_bfloat16 ha = __float2bfloat16(a);
            __nv_bfloat16 hb = __float2bfloat16(b);
            float la = a - __bfloat162float(ha);
            float lb = b - __bfloat162float(hb);
            hp[j] = pkbf(ha, hb);
            lp[j] = pkbf(__float2bfloat16(la), __float2bfloat16(lb));
        }
        uint32_t ah = sb + buf * 2 * 10240 + r * 80 + h * 32;
        sts128(ah, hp[0], hp[1], hp[2], hp[3]);
        sts128(ah + 16, hp[4], hp[5], hp[6], hp[7]);
        sts128(ah + 10240, lp[0], lp[1], lp[2], lp[3]);
        sts128(ah + 10240 + 16, lp[4], lp[5], lp[6], lp[7]);
    };

    auto cpB = [&](int ch, int buf) {
        uint32_t base = sb + 40960 + buf * 2 * 12800;
#pragma unroll
        for (int it = 0; it < 5; it++) {
            int f = tid + 256 * it;           // 0..1279
            int sel = (f >= 640) ? 1 : 0;
            int idx = f - sel * 640;
            int row = idx >> 2, q = idx & 3;
            const __nv_bfloat16* src = (sel ? Blo : Bhi) +
                (size_t)(nb0 + row) * KP + ch * 32 + q * 8;
            cpa16(base + sel * 12800 + row * 80 + q * 16, src);
        }
    };

    auto compute = [&](int buf) {
        uint32_t aBH = sb + buf * 2 * 10240 + (wm * 64 + g) * 80 + t * 4;
        uint32_t aBL = aBH + 10240;
        uint32_t bBH = sb + 40960 + buf * 2 * 12800 + (wn * 40 + g) * 80 + t * 4;
        uint32_t bBL = bBH + 12800;
#pragma unroll
        for (int ks = 0; ks < 2; ks++) {
            uint32_t ko = ks * 32;
            uint32_t aH[16], aL[16], bb[10];
#pragma unroll
            for (int i = 0; i < 4; i++) {
                uint32_t a = aBH + i * 1280 + ko;
                aH[i * 4 + 0] = lds32(a);
                aH[i * 4 + 1] = lds32(a + 640);
                aH[i * 4 + 2] = lds32(a + 16);
                aH[i * 4 + 3] = lds32(a + 656);
            }
#pragma unroll
            for (int j = 0; j < 5; j++) {
                uint32_t b = bBH + j * 640 + ko;
                bb[j * 2] = lds32(b);
                bb[j * 2 + 1] = lds32(b + 16);
            }
#pragma unroll
            for (int i = 0; i < 4; i++)
#pragma unroll
                for (int j = 0; j < 5; j++)
                    mma16816(acc[i][j], aH[i*4], aH[i*4+1], aH[i*4+2], aH[i*4+3], bb[j*2], bb[j*2+1]);
#pragma unroll
            for (int i = 0; i < 4; i++) {
                uint32_t a = aBL + i * 1280 + ko;
                aL[i * 4 + 0] = lds32(a);
                aL[i * 4 + 1] = lds32(a + 640);
                aL[i * 4 + 2] = lds32(a + 16);
                aL[i * 4 + 3] = lds32(a + 656);
            }
#pragma unroll
            for (int i = 0; i < 4; i++)
#pragma unroll
                for (int j = 0; j < 5; j++)
                    mma16816(acc[i][j], aL[i*4], aL[i*4+1], aL[i*4+2], aL[i*4+3], bb[j*2], bb[j*2+1]);
#pragma unroll
            for (int j = 0; j < 5; j++) {
                uint32_t b = bBL + j * 640 + ko;
                bb[j * 2] = lds32(b);
                bb[j * 2 + 1] = lds32(b + 16);
            }
#pragma unroll
            for (int i = 0; i < 4; i++)
#pragma unroll
                for (int j = 0; j < 5; j++)
                    mma16816(acc[i][j], aH[i*4], aH[i*4+1], aH[i*4+2], aH[i*4+3], bb[j*2], bb[j*2+1]);
        }
    };

    // prologue
    loadA(0);
    cpB(0, 0);
    cpa_commit();
    storeA(0);

    for (int ch = 0; ch < NCH; ch++) {
        bool nxt = (ch + 1 < NCH);
        if (nxt) loadA(ch + 1);
        cpa_wait0();
        __syncthreads();
        if (nxt) {
            cpB(ch + 1, (ch + 1) & 1);
            cpa_commit();
            storeA((ch + 1) & 1);
        }
        compute(ch & 1);
    }

    // epilogue
    int rowBase = blockIdx.y * 128 + wm * 64 + g;
    int colBase = nb0 + wn * 40 + t * 2;
#pragma unroll
    for (int i = 0; i < 4; i++) {
        int row = rowBase + i * 16;
#pragma unroll
        for (int j = 0; j < 5; j++) {
            int col = colBase + j * 8;
            size_t o0 = (size_t)row * HP + col;
            size_t o1 = o0 + (size_t)8 * HP;
            float2 v0 = make_float2(acc[i][j][0], acc[i][j][1]);
            float2 v1 = make_float2(acc[i][j][2], acc[i][j][3]);
            if constexpr (MODE == 2) {
                *(float2*)(C0 + o0) = v0;
                *(float2*)(C0 + o1) = v1;
                *(float2*)(C1 + o0) = make_float2(fmaxf(v0.x, 0.f), fmaxf(v0.y, 0.f));
                *(float2*)(C1 + o1) = make_float2(fmaxf(v1.x, 0.f), fmaxf(v1.y, 0.f));
            } else if constexpr (MODE == 1) {
                float2 i0 = *(const float2*)(inp + o0);
                float2 i1 = *(const float2*)(inp + o1);
                *(float2*)(C0 + o0) = make_float2(fmaxf(v0.x + i0.x, 0.f), fmaxf(v0.y + i0.y, 0.f));
                *(float2*)(C0 + o1) = make_float2(fmaxf(v1.x + i1.x, 0.f), fmaxf(v1.y + i1.y, 0.f));
            } else {
                float b0 = bias[col], b1 = bias[col + 1];
                *(float2*)(C0 + o0) = make_float2(fmaxf(v0.x + b0, 0.f), fmaxf(v0.y + b1, 0.f));
                *(float2*)(C0 + o1) = make_float2(fmaxf(v1.x + b0, 0.f), fmaxf(v1.y + b1, 0.f));
            }
        }
    }
}

// ---------------- weight prep: transpose + pad + bf16 hi/lo split ----------------
__global__ void k_prep_wT(const float* __restrict__ W, __nv_bfloat16* __restrict__ Thi,
                          __nv_bfloat16* __restrict__ Tlo, int Kreal, int KP) {
    int idx = blockIdx.x * blockDim.x + threadIdx.x;  // HP*KP exact
    int n = idx / KP, k = idx % KP;
    float vv = (k < Kreal && n < HIDDEN) ? W[k * HIDDEN + n] : 0.f;
    __nv_bfloat16 hi = __float2bfloat16(vv);
    Thi[idx] = hi;
    Tlo[idx] = __float2bfloat16(vv - __bfloat162float(hi));
}

__global__ void k_pad_bo(const float* __restrict__ b, float* __restrict__ bp) {
    int i = threadIdx.x;
    if (i < HP) bp[i] = (i < HIDDEN) ? b[i] : 0.f;
}

// ---------------- neighbor sum ----------------
__global__ void k_nodesum(const float* __restrict__ msg, const int* __restrict__ n2e,
                          float* __restrict__ nmsg) {
    int idx = blockIdx.x * blockDim.x + threadIdx.x;
    int v = idx / (HP / 4);
    int q = (idx % (HP / 4)) * 4;
    const int* nb = n2e + v * MAXNB;
    float4 s = make_float4(0.f, 0.f, 0.f, 0.f);
#pragma unroll
    for (int j = 0; j < MAXNB; j++) {
        int e = __ldg(nb + j);
        float4 a = *reinterpret_cast<const float4*>(msg + (size_t)e * HP + q);
        s.x += a.x; s.y += a.y; s.z += a.z; s.w += a.w;
    }
    *reinterpret_cast<float4*>(nmsg + (size_t)v * HP + q) = s;
}

// ---------------- per-molecule mean (deterministic; mol_ids sorted) ----------------
__global__ void k_segmean(const float* __restrict__ hid, const int* __restrict__ mol,
                          float* __restrict__ out) {
    int m = blockIdx.x;
    int c = threadIdx.x;
    int lo = 0, hi = NNODE;
    while (lo < hi) { int mid = (lo + hi) >> 1; if (__ldg(mol + mid) < m) lo = mid + 1; else hi = mid; }
    int start = lo;
    lo = start; hi = NNODE;
    while (lo < hi) { int mid = (lo + hi) >> 1; if (__ldg(mol + mid) < m + 1) lo = mid + 1; else hi = mid; }
    int end = lo;
    if (c >= HIDDEN) return;
    float s = 0.f;
    for (int v = start; v < end; v++) s += hid[(size_t)v * HP + c];
    out[(size_t)m * HIDDEN + c] = (end > start) ? s / (float)(end - start) : 0.f;
}

// ---------------- launch ----------------
extern "C" void kernel_launch(void* const* d_in, const int* in_sizes, int n_in,
                              void* d_out, int out_size) {
    const float* f_nodes = (const float*)d_in[0];
    const float* f_edges = (const float*)d_in[1];
    const float* W_i     = (const float*)d_in[2];
    const float* W_h     = (const float*)d_in[3];
    const float* W_o     = (const float*)d_in[4];
    const float* b_o     = (const float*)d_in[5];
    const int*   n2e     = (const int*)d_in[6];
    const int*   e2n     = (const int*)d_in[7];
    const int*   e2rev   = (const int*)d_in[8];
    const int*   mol     = (const int*)d_in[9];
    float* out = (float*)d_out;

    float *inp, *msgA, *msgB, *nmsg, *hid, *bop;
    __nv_bfloat16 *WiH, *WiL, *WhH, *WhL, *WoH, *WoL;
    cudaGetSymbolAddress((void**)&inp,  g_inp);
    cudaGetSymbolAddress((void**)&msgA, g_msgA);
    cudaGetSymbolAddress((void**)&msgB, g_msgB);
    cudaGetSymbolAddress((void**)&nmsg, g_nmsg);
    cudaGetSymbolAddress((void**)&hid,  g_hid);
    cudaGetSymbolAddress((void**)&bop,  g_bop);
    cudaGetSymbolAddress((void**)&WiH,  g_WiH);
    cudaGetSymbolAddress((void**)&WiL,  g_WiL);
    cudaGetSymbolAddress((void**)&WhH,  g_WhH);
    cudaGetSymbolAddress((void**)&WhL,  g_WhL);
    cudaGetSymbolAddress((void**)&WoH,  g_WoH);
    cudaGetSymbolAddress((void**)&WoL,  g_WoL);

    cudaFuncSetAttribute(k_mma<1, KP_H>, cudaFuncAttributeMaxDynamicSharedMemorySize, SMEM_SZ);
    cudaFuncSetAttribute(k_mma<2, KP_I>, cudaFuncAttributeMaxDynamicSharedMemorySize, SMEM_SZ);
    cudaFuncSetAttribute(k_mma<3, KP_O>, cudaFuncAttributeMaxDynamicSharedMemorySize, SMEM_SZ);

    k_prep_wT<<<(HP * KP_I) / 256, 256>>>(W_i, WiH, WiL, EDGE_FDIM, KP_I);
    k_prep_wT<<<(HP * KP_H) / 256, 256>>>(W_h, WhH, WhL, HIDDEN, KP_H);
    k_prep_wT<<<(HP * KP_O) / 256, 256>>>(W_o, WoH, WoL, NODE_FDIM + HIDDEN, KP_O);
    k_pad_bo<<<1, HP>>>(b_o, bop);

    dim3 gridE(2, NEDGE / 128);
    dim3 gridN(2, NNODE / 128);

    // inp = f_edges @ W_i ; msgA = relu(inp)
    k_mma<2, KP_I><<<gridE, 256, SMEM_SZ>>>(
        f_edges, WiH, WiL, nullptr, nullptr, inp, msgA,
        nullptr, nullptr, nullptr, nullptr);

    float* cur = msgA;
    float* nxt = msgB;
    for (int it = 0; it < 5; it++) {
        k_nodesum<<<(NNODE * (HP / 4)) / 256, 256>>>(cur, n2e, nmsg);
        k_mma<1, KP_H><<<gridE, 256, SMEM_SZ>>>(
            nullptr, WhH, WhL, inp, nullptr, nxt, nullptr,
            e2n, e2rev, nmsg, cur);
        float* tmp = cur; cur = nxt; nxt = tmp;
    }

    k_nodesum<<<(NNODE * (HP / 4)) / 256, 256>>>(cur, n2e, nmsg);
    k_mma<3, KP_O><<<gridN, 256, SMEM_SZ>>>(
        f_nodes, WoH, WoL, nullptr, bop, hid, nullptr,
        nullptr, nullptr, nmsg, nullptr);

    k_segmean<<<NMOL, HP>>>(hid, mol, out);
}